// round 10
// baseline (speedup 1.0000x reference)
#include <cuda_runtime.h>
#include <cuda_fp16.h>
#include <stdint.h>

// ===========================================================================
// Problem constants
// ===========================================================================
static constexpr int  Dd    = 384;
static constexpr long KTOT  = 147456;             // D*D

// Wide GEMM tiling (legacy HMMA path: mma.sync.m16n8k16)
static constexpr int KC     = 64;                 // k per chunk (4 k16 steps)
static constexpr int NCHUNK = 2304;               // KTOT / KC
static constexpr int DEPTH  = 6;                  // B ring depth (== chunks per p)
static constexpr int PF     = 5;                  // prefetch distance
static constexpr int TILEB  = 48 * 128;           // 6144 B per B tile (contiguous)

// fp16 copy of W_L2, TILED+SWIZZLED layout:
//   tile (T = n/48, c = chunk) at byte offset (T*NCHUNK + c)*6144
//   within tile: row r (=n%48), 16B seg s (=k/8 within chunk):
//   offset = r*128 + ((s ^ (r&7)) * 16)
__device__ __align__(16) __half g_W2h[113246208];

// ===========================================================================
// PTX helpers (baseline compute_103 features only: sm_90-era, no 'a')
// ===========================================================================
static __device__ __forceinline__ uint32_t smem_u32(const void* p) {
    uint32_t a;
    asm("{ .reg .u64 t; cvta.to.shared.u64 t, %1; cvt.u32.u64 %0, t; }" : "=r"(a) : "l"(p));
    return a;
}

#define MBAR_INIT(mbar, cnt) \
    asm volatile("mbarrier.init.shared.b64 [%0], %1;" \
                 :: "r"((uint32_t)(mbar)), "r"((uint32_t)(cnt)) : "memory")

#define MBAR_EXPECT_TX(mbar, bytes) \
    asm volatile("mbarrier.arrive.expect_tx.shared.b64 _, [%0], %1;" \
                 :: "r"((uint32_t)(mbar)), "r"((uint32_t)(bytes)) : "memory")

static __device__ __forceinline__ void mbar_wait(uint32_t mbar, uint32_t parity) {
    asm volatile(
        "{\n\t.reg .pred P;\n\t"
        "WL%=:\n\t"
        "mbarrier.try_wait.parity.acquire.cta.shared::cta.b64 P, [%0], %1;\n\t"
        "@!P bra WL%=;\n\t"
        "}"
        :: "r"(mbar), "r"(parity) : "memory");
}

static __device__ __forceinline__ void bulk_copy(uint32_t dst_smem, const void* src,
                                                 uint32_t bytes, uint32_t mbar) {
    asm volatile(
        "cp.async.bulk.shared::cta.global.mbarrier::complete_tx::bytes [%0], [%1], %2, [%3];"
        :: "r"(dst_smem), "l"(src), "r"(bytes), "r"(mbar) : "memory");
}

#define FENCE_PROXY_ASYNC() asm volatile("fence.proxy.async.shared::cta;" ::: "memory")

#define LDSM_X4(b0, b1, b2, b3, addr) \
    asm volatile("ldmatrix.sync.aligned.m8n8.x4.shared.b16 {%0,%1,%2,%3}, [%4];" \
                 : "=r"(b0), "=r"(b1), "=r"(b2), "=r"(b3) : "r"(addr))

// fp16-accumulate HMMA: D,C are 2 regs (4 halves), 2x rate vs f32-accum
#define MMA16816H(d, a0, a1, a2, a3, b0, b1) \
    asm volatile("mma.sync.aligned.m16n8k16.row.col.f16.f16.f16.f16 " \
                 "{%0,%1}, {%2,%3,%4,%5}, {%6,%7}, {%0,%1};" \
                 : "+r"((d)[0]), "+r"((d)[1]) \
                 : "r"(a0), "r"(a1), "r"(a2), "r"(a3), "r"(b0), "r"(b1))

static __device__ __forceinline__ uint32_t h2u(__half2 v) {
    return *reinterpret_cast<uint32_t*>(&v);
}

// ===========================================================================
// Kernel 1: W_L2 f32 -> f16, written in TILED+SWIZZLED layout (DRAM-bound)
// ===========================================================================
__global__ __launch_bounds__(256) void convert_kernel(const float* __restrict__ W) {
    const long total = 768L * (KTOT / 8);          // 16B segs
    const long stride = (long)gridDim.x * blockDim.x;
    for (long g = (long)blockIdx.x * blockDim.x + threadIdx.x; g < total; g += stride) {
        int  n  = (int)(g / 18432);                // 18432 = KTOT/8
        int  ks = (int)(g - (long)n * 18432);
        int  c  = ks >> 3;
        int  s  = ks & 7;
        int  T  = n / 48;
        int  r  = n - T * 48;

        const float4* src = reinterpret_cast<const float4*>(
            W + (size_t)n * KTOT + ((size_t)c << 6) + (s << 3));
        float4 a = src[0];
        float4 b = src[1];
        __half2 h0 = __floats2half2_rn(a.x, a.y);
        __half2 h1 = __floats2half2_rn(a.z, a.w);
        __half2 h2 = __floats2half2_rn(b.x, b.y);
        __half2 h3 = __floats2half2_rn(b.z, b.w);
        uint4 v;
        v.x = h2u(h0); v.y = h2u(h1); v.z = h2u(h2); v.w = h2u(h3);

        size_t dst = (size_t)(T * NCHUNK + c) * TILEB
                   + (size_t)r * 128 + (size_t)((s ^ (r & 7)) << 4);
        *reinterpret_cast<uint4*>(reinterpret_cast<char*>(g_W2h) + dst) = v;
    }
}

// ===========================================================================
// Kernel 2: wide path u = v @ W_L2^T + b_L2
//   v[b, p*384+q] = hs[b,p] * ht[b,q]   (A generated in registers)
//   grid = 128 CTAs (8 m-tiles of 128 x 16 n-tiles of 48), 256 threads.
//   fp16-accumulate HMMA within each 64-K chunk, promoted to f32 per chunk.
// ===========================================================================
__global__ __launch_bounds__(256, 1) void wide_kernel(const float* __restrict__ hs,
                                                      const float* __restrict__ ht,
                                                      const float* __restrict__ bL2,
                                                      float* __restrict__ out) {
    __shared__ __align__(16) char ring[DEPTH][TILEB];        // 36864 B
    __shared__ __align__(8)  unsigned long long mbar[DEPTH]; // 6 mbarriers

    const int tid  = threadIdx.x;
    const int wid  = tid >> 5;
    const int lane = tid & 31;

    const int mt = blockIdx.x >> 4;          // 0..7
    const int nt = blockIdx.x & 15;          // 0..15
    const int n0 = nt * 48;

    // this thread's two A rows (mma m16n8k16 fragment rows)
    const int r0 = mt * 128 + wid * 16 + (lane >> 2);
    const int r1 = r0 + 8;
    const int qo = 2 * (lane & 3);           // fragment k offset within k16

    const uint32_t ring0 = smem_u32(ring[0]);
    const uint32_t mb0   = smem_u32(&mbar[0]);

    if (tid == 0) {
#pragma unroll
        for (int s = 0; s < DEPTH; s++) MBAR_INIT(mb0 + s * 8, 1);
    }
    FENCE_PROXY_ASYNC();
    __syncthreads();

    // B tile source base for this n-tile (tiled+swizzled layout)
    const char* Wt = reinterpret_cast<const char*>(g_W2h) + (size_t)nt * NCHUNK * TILEB;

    // prologue: prefetch chunks 0..PF-1 into slots 0..PF-1
    if (tid == 0) {
#pragma unroll
        for (int c = 0; c < PF; c++) {
            MBAR_EXPECT_TX(mb0 + c * 8, TILEB);
            bulk_copy(ring0 + c * TILEB, Wt + (size_t)c * TILEB, TILEB, mb0 + c * 8);
        }
    }

    // ---- resident ht fragments in registers: 2 rows x 24 blocks x 2 half2 ----
    __half2 htA[48], htB[48];
    {
        const float* htr0 = ht + (size_t)r0 * Dd;
        const float* htr1 = ht + (size_t)r1 * Dd;
#pragma unroll
        for (int blk = 0; blk < 24; blk++) {
            float2 f;
            f = *reinterpret_cast<const float2*>(htr0 + blk * 16 + qo);
            htA[blk * 2 + 0] = __floats2half2_rn(f.x, f.y);
            f = *reinterpret_cast<const float2*>(htr0 + blk * 16 + qo + 8);
            htA[blk * 2 + 1] = __floats2half2_rn(f.x, f.y);
            f = *reinterpret_cast<const float2*>(htr1 + blk * 16 + qo);
            htB[blk * 2 + 0] = __floats2half2_rn(f.x, f.y);
            f = *reinterpret_cast<const float2*>(htr1 + blk * 16 + qo + 8);
            htB[blk * 2 + 1] = __floats2half2_rn(f.x, f.y);
        }
    }

    float acc[6][4];
#pragma unroll
    for (int t = 0; t < 6; t++)
#pragma unroll
        for (int c = 0; c < 4; c++) acc[t][c] = 0.0f;

    // ldmatrix lane addressing (swizzled layout): row base + seg^row XOR
    const uint32_t rowoff = (uint32_t)((lane & 7) * 128);
    const uint32_t x0 = (uint32_t)((((lane >> 3)    ) ^ (lane & 7)) * 16);
    const uint32_t x1 = (uint32_t)((((lane >> 3) + 4) ^ (lane & 7)) * 16);

    const float* hsr0 = hs + (size_t)r0 * Dd;
    const float* hsr1 = hs + (size_t)r1 * Dd;

    // ---- main loop: 384 p values x 6 chunks of 64 q ----
    for (int p = 0; p < Dd; p++) {
        __half2 h0 = __half2half2(__float2half_rn(__ldg(hsr0 + p)));
        __half2 h1 = __half2half2(__float2half_rn(__ldg(hsr1 + p)));
        const uint32_t par = (uint32_t)(p & 1);

#pragma unroll
        for (int c2 = 0; c2 < 6; c2++) {
            const int i = p * 6 + c2;            // global chunk; i % 6 == c2

            // all warps done with chunk i-1 => slot (i-1)%6 reusable
            __syncthreads();

            if (tid == 0) {
                int nc = i + PF;
                if (nc < NCHUNK) {
                    int sl = (c2 + PF) % DEPTH;  // == nc % 6
                    MBAR_EXPECT_TX(mb0 + sl * 8, TILEB);
                    bulk_copy(ring0 + sl * TILEB, Wt + (size_t)nc * TILEB,
                              TILEB, mb0 + sl * 8);
                }
            }

            // A fragments for 4 k16-steps (pure register math)
            uint32_t a[4][4];
#pragma unroll
            for (int s = 0; s < 4; s++) {
                const int blk = c2 * 4 + s;
                a[s][0] = h2u(__hmul2(h0, htA[blk * 2 + 0]));  // row r0, k lo
                a[s][1] = h2u(__hmul2(h1, htB[blk * 2 + 0]));  // row r1, k lo
                a[s][2] = h2u(__hmul2(h0, htA[blk * 2 + 1]));  // row r0, k hi
                a[s][3] = h2u(__hmul2(h1, htB[blk * 2 + 1]));  // row r1, k hi
            }

            // wait B tile for chunk i
            mbar_wait(mb0 + c2 * 8, par);

            const uint32_t sbase = ring0 + (uint32_t)(c2 * TILEB) + rowoff;
#pragma unroll
            for (int t = 0; t < 6; t++) {
                uint32_t b0, b1, b2, b3, b4, b5, b6, b7;
                LDSM_X4(b0, b1, b2, b3, sbase + (uint32_t)(t * 1024) + x0); // ksteps 0,1
                LDSM_X4(b4, b5, b6, b7, sbase + (uint32_t)(t * 1024) + x1); // ksteps 2,3

                // fp16 accumulator, live only within this 64-K chunk
                uint32_t hacc[2];
                hacc[0] = 0u; hacc[1] = 0u;
                MMA16816H(hacc, a[0][0], a[0][1], a[0][2], a[0][3], b0, b1);
                MMA16816H(hacc, a[1][0], a[1][1], a[1][2], a[1][3], b2, b3);
                MMA16816H(hacc, a[2][0], a[2][1], a[2][2], a[2][3], b4, b5);
                MMA16816H(hacc, a[3][0], a[3][1], a[3][2], a[3][3], b6, b7);

                // promote chunk partial to f32
                float2 f0 = __half22float2(*reinterpret_cast<__half2*>(&hacc[0]));
                float2 f1 = __half22float2(*reinterpret_cast<__half2*>(&hacc[1]));
                acc[t][0] += f0.x;
                acc[t][1] += f0.y;
                acc[t][2] += f1.x;
                acc[t][3] += f1.y;
            }
        }
    }

    // ---- epilogue: add bias, store (float2 per row per n8-tile) ----
#pragma unroll
    for (int t = 0; t < 6; t++) {
        const int n = n0 + t * 8 + qo;
        float2 bb = *reinterpret_cast<const float2*>(bL2 + n);
        float2 v0 = make_float2(acc[t][0] + bb.x, acc[t][1] + bb.y);
        float2 v1 = make_float2(acc[t][2] + bb.x, acc[t][3] + bb.y);
        *reinterpret_cast<float2*>(out + (size_t)r0 * 1536 + 768 + n) = v0;
        *reinterpret_cast<float2*>(out + (size_t)r1 * 1536 + 768 + n) = v1;
    }
}

// ===========================================================================
// Kernel 3: deep path g = cat(hs,ht) @ W_L^T + b_L  (exact f32, 64x64 tiles)
// grid = (16, 12), 256 threads
// ===========================================================================
__global__ __launch_bounds__(256) void deep_kernel(const float* __restrict__ hs,
                                                   const float* __restrict__ ht,
                                                   const float* __restrict__ WL,
                                                   const float* __restrict__ bL,
                                                   float* __restrict__ out) {
    __shared__ float As[16][64];
    __shared__ float Bs[16][64];
    const int tid = threadIdx.x;
    const int m0 = blockIdx.x * 64;
    const int n0 = blockIdx.y * 64;
    const int ty = tid >> 4;
    const int tx = tid & 15;

    float acc[4][4] = {};

    for (int kk = 0; kk < 768; kk += 16) {
#pragma unroll
        for (int l = 0; l < 4; l++) {
            int i = tid + l * 256;
            int r = i >> 4;
            int c = i & 15;
            int k = kk + c;
            float av = (k < 384) ? hs[(size_t)(m0 + r) * 384 + k]
                                 : ht[(size_t)(m0 + r) * 384 + (k - 384)];
            As[c][r] = av;
            Bs[c][r] = WL[(size_t)(n0 + r) * 768 + k];
        }
        __syncthreads();
#pragma unroll
        for (int k = 0; k < 16; k++) {
            float4 a4 = *reinterpret_cast<const float4*>(&As[k][ty * 4]);
            float4 b4 = *reinterpret_cast<const float4*>(&Bs[k][tx * 4]);
            float a[4] = {a4.x, a4.y, a4.z, a4.w};
            float b[4] = {b4.x, b4.y, b4.z, b4.w};
#pragma unroll
            for (int i2 = 0; i2 < 4; i2++)
#pragma unroll
                for (int j = 0; j < 4; j++) acc[i2][j] += a[i2] * b[j];
        }
        __syncthreads();
    }

#pragma unroll
    for (int i2 = 0; i2 < 4; i2++) {
        int m = m0 + ty * 4 + i2;
#pragma unroll
        for (int j = 0; j < 4; j++) {
            int n = n0 + tx * 4 + j;
            out[(size_t)m * 1536 + n] = acc[i2][j] + bL[n];
        }
    }
}

// ===========================================================================
// kernel_launch
// Inputs (metadata order): hspatial, htext, W_L, b_L, W_L2, b_L2. Output f32.
// ===========================================================================
extern "C" void kernel_launch(void* const* d_in, const int* in_sizes, int n_in,
                              void* d_out, int out_size) {
    const float* hs  = (const float*)d_in[0];
    const float* ht  = (const float*)d_in[1];
    const float* WL  = (const float*)d_in[2];
    const float* bL  = (const float*)d_in[3];
    const float* WL2 = (const float*)d_in[4];
    const float* bL2 = (const float*)d_in[5];
    float* out = (float*)d_out;

    // 1) W_L2 -> fp16 scratch, tiled+swizzled (streaming, ~98 us)
    convert_kernel<<<2048, 256>>>(WL2);

    // 2) wide path (HMMA fp16-accum, A in registers, B via cp.async.bulk)
    wide_kernel<<<128, 256>>>(hs, ht, bL2, out);

    // 3) deep path (exact f32)
    dim3 dgrid(16, 12);
    deep_kernel<<<dgrid, 256>>>(hs, ht, WL, bL, out);
}

// round 11
// speedup vs baseline: 1.1823x; 1.1823x over previous
#include <cuda_runtime.h>
#include <cuda_fp16.h>
#include <stdint.h>

// ===========================================================================
// Problem constants
// ===========================================================================
static constexpr int  Dd    = 384;
static constexpr long KTOT  = 147456;             // D*D

// Wide GEMM tiling (legacy HMMA path: mma.sync.m16n8k16, f32 accum)
static constexpr int KC     = 64;                 // k per chunk (4 k16 steps)
static constexpr int NCHUNK = 2304;               // KTOT / KC
static constexpr int DEPTH  = 6;                  // B ring depth (== chunks per p)
static constexpr int PF     = 5;                  // prefetch distance
static constexpr int TILEB  = 48 * 128;           // 6144 B per B tile (contiguous)

// K-split: 8 slices of 48 p-values (288 chunks) each
static constexpr int KSPLIT = 8;
static constexpr int PSLICE = Dd / KSPLIT;        // 48
static constexpr int NWIDE  = 8 * 16 * KSPLIT;    // 1024 wide units
static constexpr int NDEEP  = 16 * 12;            // 192 deep tiles

// fp16 copy of W_L2, TILED+SWIZZLED layout:
//   tile (T = n/48, c = chunk) at byte offset (T*NCHUNK + c)*6144
//   within tile: row r (=n%48), 16B seg s (=k/8 within chunk):
//   offset = r*128 + ((s ^ (r&7)) * 16)
__device__ __align__(16) __half g_W2h[113246208];

// per-K-slice partial accumulators (deterministic, no atomics): [8][1024][768]
__device__ __align__(16) float g_part[KSPLIT * 1024 * 768];

// ===========================================================================
// PTX helpers (baseline compute_103 features only: sm_90-era, no 'a')
// ===========================================================================
static __device__ __forceinline__ uint32_t smem_u32(const void* p) {
    uint32_t a;
    asm("{ .reg .u64 t; cvta.to.shared.u64 t, %1; cvt.u32.u64 %0, t; }" : "=r"(a) : "l"(p));
    return a;
}

#define MBAR_INIT(mbar, cnt) \
    asm volatile("mbarrier.init.shared.b64 [%0], %1;" \
                 :: "r"((uint32_t)(mbar)), "r"((uint32_t)(cnt)) : "memory")

#define MBAR_EXPECT_TX(mbar, bytes) \
    asm volatile("mbarrier.arrive.expect_tx.shared.b64 _, [%0], %1;" \
                 :: "r"((uint32_t)(mbar)), "r"((uint32_t)(bytes)) : "memory")

static __device__ __forceinline__ void mbar_wait(uint32_t mbar, uint32_t parity) {
    asm volatile(
        "{\n\t.reg .pred P;\n\t"
        "WL%=:\n\t"
        "mbarrier.try_wait.parity.acquire.cta.shared::cta.b64 P, [%0], %1;\n\t"
        "@!P bra WL%=;\n\t"
        "}"
        :: "r"(mbar), "r"(parity) : "memory");
}

static __device__ __forceinline__ void bulk_copy(uint32_t dst_smem, const void* src,
                                                 uint32_t bytes, uint32_t mbar) {
    asm volatile(
        "cp.async.bulk.shared::cta.global.mbarrier::complete_tx::bytes [%0], [%1], %2, [%3];"
        :: "r"(dst_smem), "l"(src), "r"(bytes), "r"(mbar) : "memory");
}

#define FENCE_PROXY_ASYNC() asm volatile("fence.proxy.async.shared::cta;" ::: "memory")

#define LDSM_X4(b0, b1, b2, b3, addr) \
    asm volatile("ldmatrix.sync.aligned.m8n8.x4.shared.b16 {%0,%1,%2,%3}, [%4];" \
                 : "=r"(b0), "=r"(b1), "=r"(b2), "=r"(b3) : "r"(addr))

#define MMA16816(d, a0, a1, a2, a3, b0, b1) \
    asm volatile("mma.sync.aligned.m16n8k16.row.col.f32.f16.f16.f32 " \
                 "{%0,%1,%2,%3}, {%4,%5,%6,%7}, {%8,%9}, {%0,%1,%2,%3};" \
                 : "+f"((d)[0]), "+f"((d)[1]), "+f"((d)[2]), "+f"((d)[3]) \
                 : "r"(a0), "r"(a1), "r"(a2), "r"(a3), "r"(b0), "r"(b1))

static __device__ __forceinline__ uint32_t h2u(__half2 v) {
    return *reinterpret_cast<uint32_t*>(&v);
}

// ===========================================================================
// Kernel 1: W_L2 f32 -> f16, written in TILED+SWIZZLED layout (DRAM-bound)
// ===========================================================================
__global__ __launch_bounds__(256) void convert_kernel(const float* __restrict__ W) {
    const long total = 768L * (KTOT / 8);          // 16B segs
    const long stride = (long)gridDim.x * blockDim.x;
    for (long g = (long)blockIdx.x * blockDim.x + threadIdx.x; g < total; g += stride) {
        int  n  = (int)(g / 18432);                // 18432 = KTOT/8
        int  ks = (int)(g - (long)n * 18432);
        int  c  = ks >> 3;
        int  s  = ks & 7;
        int  T  = n / 48;
        int  r  = n - T * 48;

        const float4* src = reinterpret_cast<const float4*>(
            W + (size_t)n * KTOT + ((size_t)c << 6) + (s << 3));
        float4 a = src[0];
        float4 b = src[1];
        __half2 h0 = __floats2half2_rn(a.x, a.y);
        __half2 h1 = __floats2half2_rn(a.z, a.w);
        __half2 h2 = __floats2half2_rn(b.x, b.y);
        __half2 h3 = __floats2half2_rn(b.z, b.w);
        uint4 v;
        v.x = h2u(h0); v.y = h2u(h1); v.z = h2u(h2); v.w = h2u(h3);

        size_t dst = (size_t)(T * NCHUNK + c) * TILEB
                   + (size_t)r * 128 + (size_t)((s ^ (r & 7)) << 4);
        *reinterpret_cast<uint4*>(reinterpret_cast<char*>(g_W2h) + dst) = v;
    }
}

// ===========================================================================
// Fused kernel: blocks [0,1024) = wide units, [1024,1216) = deep tiles.
//   Wide unit = (mt, nt, ksl): m-tile 128, n-tile 48, p in [ksl*48,(ksl+1)*48)
//   writes f32 partial into g_part[ksl]. Deep tile = exact f32 64x64 SGEMM.
// ===========================================================================
union SmemU {
    struct {
        char ring[DEPTH][TILEB];                 // 36864 B
        unsigned long long mbar[DEPTH];
    } w;
    struct {
        float As[16][64];
        float Bs[16][64];
    } d;
};

__global__ __launch_bounds__(256, 1) void fused_kernel(const float* __restrict__ hs,
                                                       const float* __restrict__ ht,
                                                       const float* __restrict__ WL,
                                                       const float* __restrict__ bL,
                                                       float* __restrict__ out) {
    __shared__ __align__(16) SmemU sm;

    const int tid  = threadIdx.x;

    if (blockIdx.x >= NWIDE) {
        // ------------------ deep path tile ------------------
        const int t  = blockIdx.x - NWIDE;
        const int m0 = (t & 15) * 64;
        const int n0 = (t >> 4) * 64;
        const int ty = tid >> 4;
        const int tx = tid & 15;

        float acc[4][4] = {};

        for (int kk = 0; kk < 768; kk += 16) {
#pragma unroll
            for (int l = 0; l < 4; l++) {
                int i = tid + l * 256;
                int r = i >> 4;
                int c = i & 15;
                int k = kk + c;
                float av = (k < 384) ? hs[(size_t)(m0 + r) * 384 + k]
                                     : ht[(size_t)(m0 + r) * 384 + (k - 384)];
                sm.d.As[c][r] = av;
                sm.d.Bs[c][r] = WL[(size_t)(n0 + r) * 768 + k];
            }
            __syncthreads();
#pragma unroll
            for (int k = 0; k < 16; k++) {
                float4 a4 = *reinterpret_cast<const float4*>(&sm.d.As[k][ty * 4]);
                float4 b4 = *reinterpret_cast<const float4*>(&sm.d.Bs[k][tx * 4]);
                float a[4] = {a4.x, a4.y, a4.z, a4.w};
                float b[4] = {b4.x, b4.y, b4.z, b4.w};
#pragma unroll
                for (int i2 = 0; i2 < 4; i2++)
#pragma unroll
                    for (int j = 0; j < 4; j++) acc[i2][j] += a[i2] * b[j];
            }
            __syncthreads();
        }

#pragma unroll
        for (int i2 = 0; i2 < 4; i2++) {
            int m = m0 + ty * 4 + i2;
#pragma unroll
            for (int j = 0; j < 4; j++) {
                int n = n0 + tx * 4 + j;
                out[(size_t)m * 1536 + n] = acc[i2][j] + bL[n];
            }
        }
        return;
    }

    // ------------------ wide unit ------------------
    const int wid  = tid >> 5;
    const int lane = tid & 31;

    // blockIdx = ((ksl*16 + nt)*8 + mt): consecutive ids share the B slice
    const int mt   = blockIdx.x & 7;
    const int rest = blockIdx.x >> 3;
    const int nt   = rest & 15;
    const int ksl  = rest >> 4;
    const int n0   = nt * 48;
    const int p0   = ksl * PSLICE;
    const int CEND = (p0 + PSLICE) * 6;

    // this thread's two A rows (mma m16n8k16 fragment rows)
    const int r0 = mt * 128 + wid * 16 + (lane >> 2);
    const int r1 = r0 + 8;
    const int qo = 2 * (lane & 3);           // fragment k offset within k16

    const uint32_t ring0 = smem_u32(sm.w.ring[0]);
    const uint32_t mb0   = smem_u32(&sm.w.mbar[0]);

    if (tid == 0) {
#pragma unroll
        for (int s = 0; s < DEPTH; s++) MBAR_INIT(mb0 + s * 8, 1);
    }
    FENCE_PROXY_ASYNC();
    __syncthreads();

    // B tile source base for this n-tile (tiled+swizzled layout)
    const char* Wt = reinterpret_cast<const char*>(g_W2h) + (size_t)nt * NCHUNK * TILEB;

    // prologue: prefetch chunks CBEG..CBEG+PF-1 into slots 0..PF-1
    const int CBEG = p0 * 6;
    if (tid == 0) {
#pragma unroll
        for (int c = 0; c < PF; c++) {
            MBAR_EXPECT_TX(mb0 + c * 8, TILEB);
            bulk_copy(ring0 + c * TILEB, Wt + (size_t)(CBEG + c) * TILEB,
                      TILEB, mb0 + c * 8);
        }
    }

    // ---- resident ht fragments in registers: 2 rows x 24 blocks x 2 half2 ----
    __half2 htA[48], htB[48];
    {
        const float* htr0 = ht + (size_t)r0 * Dd;
        const float* htr1 = ht + (size_t)r1 * Dd;
#pragma unroll
        for (int blk = 0; blk < 24; blk++) {
            float2 f;
            f = *reinterpret_cast<const float2*>(htr0 + blk * 16 + qo);
            htA[blk * 2 + 0] = __floats2half2_rn(f.x, f.y);
            f = *reinterpret_cast<const float2*>(htr0 + blk * 16 + qo + 8);
            htA[blk * 2 + 1] = __floats2half2_rn(f.x, f.y);
            f = *reinterpret_cast<const float2*>(htr1 + blk * 16 + qo);
            htB[blk * 2 + 0] = __floats2half2_rn(f.x, f.y);
            f = *reinterpret_cast<const float2*>(htr1 + blk * 16 + qo + 8);
            htB[blk * 2 + 1] = __floats2half2_rn(f.x, f.y);
        }
    }

    float acc[6][4];
#pragma unroll
    for (int t = 0; t < 6; t++)
#pragma unroll
        for (int c = 0; c < 4; c++) acc[t][c] = 0.0f;

    // ldmatrix lane addressing (swizzled layout): row base + seg^row XOR
    const uint32_t rowoff = (uint32_t)((lane & 7) * 128);
    const uint32_t x0 = (uint32_t)((((lane >> 3)    ) ^ (lane & 7)) * 16);
    const uint32_t x1 = (uint32_t)((((lane >> 3) + 4) ^ (lane & 7)) * 16);

    const float* hsr0 = hs + (size_t)r0 * Dd;
    const float* hsr1 = hs + (size_t)r1 * Dd;

    // ---- main loop: 48 p values x 6 chunks of 64 q ----
    for (int p = p0; p < p0 + PSLICE; p++) {
        __half2 h0 = __half2half2(__float2half_rn(__ldg(hsr0 + p)));
        __half2 h1 = __half2half2(__float2half_rn(__ldg(hsr1 + p)));
        const uint32_t par = (uint32_t)((p - p0) & 1);

#pragma unroll
        for (int c2 = 0; c2 < 6; c2++) {
            const int i = p * 6 + c2;            // global chunk; i % 6 == c2

            // all warps done with chunk i-1 => slot (i-1)%6 reusable
            __syncthreads();

            if (tid == 0) {
                int nc = i + PF;
                if (nc < CEND) {
                    int sl = (c2 + PF) % DEPTH;  // == nc % 6
                    MBAR_EXPECT_TX(mb0 + sl * 8, TILEB);
                    bulk_copy(ring0 + sl * TILEB, Wt + (size_t)nc * TILEB,
                              TILEB, mb0 + sl * 8);
                }
            }

            // A fragments for 4 k16-steps (pure register math)
            uint32_t a[4][4];
#pragma unroll
            for (int s = 0; s < 4; s++) {
                const int blk = c2 * 4 + s;
                a[s][0] = h2u(__hmul2(h0, htA[blk * 2 + 0]));  // row r0, k lo
                a[s][1] = h2u(__hmul2(h1, htB[blk * 2 + 0]));  // row r1, k lo
                a[s][2] = h2u(__hmul2(h0, htA[blk * 2 + 1]));  // row r0, k hi
                a[s][3] = h2u(__hmul2(h1, htB[blk * 2 + 1]));  // row r1, k hi
            }

            // wait B tile for chunk i
            mbar_wait(mb0 + c2 * 8, par);

            const uint32_t sbase = ring0 + (uint32_t)(c2 * TILEB) + rowoff;
#pragma unroll
            for (int t = 0; t < 6; t++) {
                uint32_t b0, b1, b2, b3, b4, b5, b6, b7;
                LDSM_X4(b0, b1, b2, b3, sbase + (uint32_t)(t * 1024) + x0); // ksteps 0,1
                LDSM_X4(b4, b5, b6, b7, sbase + (uint32_t)(t * 1024) + x1); // ksteps 2,3
                MMA16816(acc[t], a[0][0], a[0][1], a[0][2], a[0][3], b0, b1);
                MMA16816(acc[t], a[1][0], a[1][1], a[1][2], a[1][3], b2, b3);
                MMA16816(acc[t], a[2][0], a[2][1], a[2][2], a[2][3], b4, b5);
                MMA16816(acc[t], a[3][0], a[3][1], a[3][2], a[3][3], b6, b7);
            }
        }
    }

    // ---- epilogue: store f32 partial into g_part[ksl] (deterministic) ----
    float* pb = g_part + (size_t)ksl * (1024 * 768);
#pragma unroll
    for (int t = 0; t < 6; t++) {
        const int n = n0 + t * 8 + qo;
        *reinterpret_cast<float2*>(pb + (size_t)r0 * 768 + n) =
            make_float2(acc[t][0], acc[t][1]);
        *reinterpret_cast<float2*>(pb + (size_t)r1 * 768 + n) =
            make_float2(acc[t][2], acc[t][3]);
    }
}

// ===========================================================================
// Reduce kernel: out[:,768:1536] = bias + sum over 8 K-slices of g_part
// grid = 768, block = 256; float4 per thread (196608 float4 elements)
// ===========================================================================
__global__ __launch_bounds__(256) void reduce_kernel(const float* __restrict__ bL2,
                                                     float* __restrict__ out) {
    const int e4 = blockIdx.x * 256 + threadIdx.x;   // 0..196607
    const int b  = e4 / 192;                          // row
    const int n4 = e4 - b * 192;                      // float4 col
    const int n  = n4 * 4;

    float4 s = *reinterpret_cast<const float4*>(bL2 + n);
#pragma unroll
    for (int k = 0; k < KSPLIT; k++) {
        const float4 v = *reinterpret_cast<const float4*>(
            g_part + (size_t)k * (1024 * 768) + (size_t)b * 768 + n);
        s.x += v.x; s.y += v.y; s.z += v.z; s.w += v.w;
    }
    *reinterpret_cast<float4*>(out + (size_t)b * 1536 + 768 + n) = s;
}

// ===========================================================================
// kernel_launch
// Inputs (metadata order): hspatial, htext, W_L, b_L, W_L2, b_L2. Output f32.
// ===========================================================================
extern "C" void kernel_launch(void* const* d_in, const int* in_sizes, int n_in,
                              void* d_out, int out_size) {
    const float* hs  = (const float*)d_in[0];
    const float* ht  = (const float*)d_in[1];
    const float* WL  = (const float*)d_in[2];
    const float* bL  = (const float*)d_in[3];
    const float* WL2 = (const float*)d_in[4];
    const float* bL2 = (const float*)d_in[5];
    float* out = (float*)d_out;

    // 1) W_L2 -> fp16 scratch, tiled+swizzled (streaming, ~98 us)
    convert_kernel<<<2048, 256>>>(WL2);

    // 2) fused: 1024 wide K-slice units (HMMA) + 192 deep tiles, 148 SMs busy
    fused_kernel<<<NWIDE + NDEEP, 256>>>(hs, ht, WL, bL, out);

    // 3) reduce K-slice partials + bias into out
    reduce_kernel<<<768, 256>>>(bL2, out);
}